// round 11
// baseline (speedup 1.0000x reference)
#include <cuda_runtime.h>
#include <cuda_bf16.h>
#include <cuda_fp16.h>
#include <cstdint>
#include <math.h>

#define ALPHA    0.2f
#define NEG_INFV (-1000000000000.0f)
#define LOG2E_F  1.4426950408889634f

#define BATCH 4
#define NN    4096
#define FIN   256
#define FOUT  128

#define BI 64              // query rows per block
#define BJ 64              // key chunk
#define NCHUNK (NN / BJ)   // 64

#define PH_STRIDE 72       // fp16 per P row (144 B, 16B-aligned)
#define HH_STRIDE 136      // fp16 per h row (272 B, 16B-aligned)
#define HH_BUFB   (BJ * HH_STRIDE * 2)   // 17408 B per h buffer
#define PH_BUFB   (BI * PH_STRIDE * 2)   // 9216 B per P buffer

typedef unsigned long long u64;
typedef unsigned int       u32;

// scratch (device globals: allocation-free)
__device__ float    g_h   [BATCH * NN * FOUT];
__device__ __half   g_h_hi[BATCH * NN * FOUT];
__device__ float    g_s1[BATCH * NN];
__device__ float    g_s2[BATCH * NN];
__device__ unsigned g_s2max_enc[BATCH];

// ---------------------------------------------------------------------------
// helpers
// ---------------------------------------------------------------------------
__device__ __forceinline__ unsigned enc_f(float f) {
    int i = __float_as_int(f);
    unsigned u = (unsigned)i;
    return (i < 0) ? ~u : (u | 0x80000000u);
}
__device__ __forceinline__ float dec_f(unsigned u) {
    int i = (u & 0x80000000u) ? (int)(u & 0x7fffffffu) : (int)~u;
    return __int_as_float(i);
}
__device__ __forceinline__ void ffma2(u64& d, u64 a, u64 b) {
    asm("fma.rn.f32x2 %0, %1, %2, %0;" : "+l"(d) : "l"(a), "l"(b));
}
__device__ __forceinline__ u64 bcast2(float x) {
    u64 r; asm("mov.b64 %0, {%1, %1};" : "=l"(r) : "f"(x)); return r;
}
__device__ __forceinline__ float2 unpack2(u64 v) {
    float2 f; asm("mov.b64 {%0, %1}, %2;" : "=f"(f.x), "=f"(f.y) : "l"(v)); return f;
}
__device__ __forceinline__ float fexp2n(float x) {   // 2^x, x <= 0, FMA-pipe only
    x = fmaxf(x, -126.0f);
    float z = x + 12582912.0f;
    int   n = __float_as_int(z) - 0x4B400000;
    float f = x - (z - 12582912.0f);
    float p = fmaf(0.0013333558f, f, 0.0096181291f);
    p = fmaf(p, f, 0.0555041087f);
    p = fmaf(p, f, 0.2402265070f);
    p = fmaf(p, f, 0.6931471806f);
    p = fmaf(p, f, 1.0f);
    return __int_as_float((n + 127) << 23) * p;
}
__device__ __forceinline__ u32 smem_u32(const void* p) {
    u32 a;
    asm("{ .reg .u64 t; cvta.to.shared.u64 t, %1; cvt.u32.u64 %0, t; }"
        : "=r"(a) : "l"(p));
    return a;
}
__device__ __forceinline__ void cp16(u32 dst, const void* src) {
    asm volatile("cp.async.cg.shared.global [%0], [%1], 16;"
                 :: "r"(dst), "l"(src) : "memory");
}
__device__ __forceinline__ void cp4(u32 dst, const void* src) {
    asm volatile("cp.async.ca.shared.global [%0], [%1], 4;"
                 :: "r"(dst), "l"(src) : "memory");
}
#define CP_COMMIT() asm volatile("cp.async.commit_group;" ::: "memory")
#define CP_WAIT1()  asm volatile("cp.async.wait_group 1;"  ::: "memory")
#define CP_WAIT0()  asm volatile("cp.async.wait_group 0;"  ::: "memory")

__device__ __forceinline__ void ldsm_x4(u32& r0, u32& r1, u32& r2, u32& r3, u32 a) {
    asm volatile("ldmatrix.sync.aligned.m8n8.x4.shared.b16 {%0,%1,%2,%3}, [%4];"
                 : "=r"(r0), "=r"(r1), "=r"(r2), "=r"(r3) : "r"(a));
}
__device__ __forceinline__ void ldsm_x4t(u32& r0, u32& r1, u32& r2, u32& r3, u32 a) {
    asm volatile("ldmatrix.sync.aligned.m8n8.x4.trans.shared.b16 {%0,%1,%2,%3}, [%4];"
                 : "=r"(r0), "=r"(r1), "=r"(r2), "=r"(r3) : "r"(a));
}
__device__ __forceinline__ void mma16816h(float* d,
                                          u32 a0, u32 a1, u32 a2, u32 a3,
                                          u32 b0, u32 b1) {
    asm volatile("mma.sync.aligned.m16n8k16.row.col.f32.f16.f16.f32 "
                 "{%0,%1,%2,%3}, {%4,%5,%6,%7}, {%8,%9}, {%0,%1,%2,%3};"
                 : "+f"(d[0]), "+f"(d[1]), "+f"(d[2]), "+f"(d[3])
                 : "r"(a0), "r"(a1), "r"(a2), "r"(a3), "r"(b0), "r"(b1));
}

// D += P(16x64) @ H(64x128) for one warp: A from ph buffer, B from hh buffer
__device__ __forceinline__ void gemm_chunk(float (&D)[16][4],
                                           u32 ph_b, u32 hh_b,
                                           u32 aoff, u32 boff) {
#pragma unroll
    for (int ks = 0; ks < 4; ++ks) {
        u32 a0, a1, a2, a3;
        ldsm_x4(a0, a1, a2, a3, ph_b + aoff + ks * 32);
        const u32 krow = (u32)ks * 16 * (HH_STRIDE * 2);
#pragma unroll
        for (int nt2 = 0; nt2 < 8; ++nt2) {
            u32 b0, b1, b2, b3;
            ldsm_x4t(b0, b1, b2, b3, hh_b + krow + nt2 * 32 + boff);
            mma16816h(D[nt2 * 2],     a0, a1, a2, a3, b0, b1);
            mma16816h(D[nt2 * 2 + 1], a0, a1, a2, a3, b2, b3);
        }
    }
}

// ---------------------------------------------------------------------------
// Kernel 1: h = inp @ W  (fp32x2 GEMM, 32-row tiles -> 512 CTAs);
//           epilogue emits fp16 h
// ---------------------------------------------------------------------------
__global__ void __launch_bounds__(128) k_h_gemm(const float* __restrict__ inp,
                                               const float* __restrict__ W) {
    if (blockIdx.x == 0 && threadIdx.x < BATCH) g_s2max_enc[threadIdx.x] = 0u;

    __shared__ float Ws[32][128];
    __shared__ float Is[32][36];

    const int t  = threadIdx.x;
    const int tx = t & 15;
    const int ty = t >> 4;          // 0..7, rows ty*4..+3
    const int m0 = blockIdx.x * 32;

    u64 acc2[4][4];
#pragma unroll
    for (int r = 0; r < 4; ++r)
#pragma unroll
        for (int c = 0; c < 4; ++c) acc2[r][c] = 0ull;

    for (int kc = 0; kc < FIN; kc += 32) {
        __syncthreads();
#pragma unroll
        for (int r = 0; r < 8; ++r) {                 // W chunk 32x128
            int v = t + 128 * r;
            int k = v >> 5, fq = v & 31;
            *(float4*)&Ws[k][fq * 4] =
                *(const float4*)&W[(size_t)(kc + k) * FOUT + fq * 4];
        }
#pragma unroll
        for (int r = 0; r < 2; ++r) {                 // inp chunk 32x32
            int v = t + 128 * r;
            int m = v >> 3, kq = v & 7;
            *(float4*)&Is[m][kq * 4] =
                *(const float4*)&inp[(size_t)(m0 + m) * FIN + kc + kq * 4];
        }
        __syncthreads();

#pragma unroll
        for (int k = 0; k < 32; ++k) {
            u64 wv2[4];
            {
                ulonglong2 w01 = *(const ulonglong2*)&Ws[k][tx * 4];
                ulonglong2 w23 = *(const ulonglong2*)&Ws[k][64 + tx * 4];
                wv2[0] = w01.x; wv2[1] = w01.y; wv2[2] = w23.x; wv2[3] = w23.y;
            }
            u64 iv2[4];
#pragma unroll
            for (int r = 0; r < 4; ++r) iv2[r] = bcast2(Is[ty * 4 + r][k]);
#pragma unroll
            for (int r = 0; r < 4; ++r)
#pragma unroll
                for (int c = 0; c < 4; ++c)
                    ffma2(acc2[r][c], iv2[r], wv2[c]);
        }
    }

#pragma unroll
    for (int r = 0; r < 4; ++r)
#pragma unroll
        for (int c = 0; c < 4; ++c) {
            int f = (c < 2) ? (tx * 4 + 2 * c) : (64 + tx * 4 + 2 * (c - 2));
            size_t idx = (size_t)(m0 + ty * 4 + r) * FOUT + f;
            float2 v = unpack2(acc2[r][c]);
            g_h[idx]     = v.x;
            g_h[idx + 1] = v.y;
            *(__half2*)&g_h_hi[idx] = __floats2half2_rn(v.x, v.y);
        }
}

// ---------------------------------------------------------------------------
// Kernel 1b: s1, s2, batchwise max(s2)
// ---------------------------------------------------------------------------
__global__ void __launch_bounds__(128) k_scores(const float* __restrict__ a) {
    const int row  = blockIdx.x * 4 + (threadIdx.x >> 5);
    const int lane = threadIdx.x & 31;
    const float* hr = g_h + (size_t)row * FOUT;
    float s1 = 0.f, s2 = 0.f;
#pragma unroll
    for (int k = 0; k < 4; ++k) {
        float hv = hr[lane + 32 * k];
        s1 = fmaf(hv, a[lane + 32 * k], s1);
        s2 = fmaf(hv, a[FOUT + lane + 32 * k], s2);
    }
#pragma unroll
    for (int off = 16; off; off >>= 1) {
        s1 += __shfl_xor_sync(0xffffffffu, s1, off);
        s2 += __shfl_xor_sync(0xffffffffu, s2, off);
    }
    if (lane == 0) {
        g_s1[row] = s1;
        g_s2[row] = s2;
        atomicMax(&g_s2max_enc[row / NN], enc_f(s2));
    }
}

// ---------------------------------------------------------------------------
// Kernel 2: software-pipelined — chunk c runs logit(c) then GEMM(c-1) with
// no barrier between them (FMA + tensor pipes overlap). ONE __syncthreads
// per chunk, placed immediately AFTER cp.async.wait_group at chunk top:
// that is what publishes adj(c), h(c-1) (cross-thread cp.async visibility!)
// and the previous chunk's ph writes before any consumer touches them.
// ph double-buffered, hh triple-buffered, adj double-buffered.
// ---------------------------------------------------------------------------
struct AttnSmem {
    __half hh[3][BJ][HH_STRIDE];       // 52224 B
    __half ph[2][BI][PH_STRIDE];       // 18432
    float adjb[2][BI][BJ];             // 32768
    float s2s[2][BJ];                  //   512
    float s1s[BI];                     //   256
    float bss[BI];                     //   256
    float l[BI];                       //   256
};

__global__ void __launch_bounds__(128, 2) k_attn(const float* __restrict__ adj,
                                                 float* __restrict__ out) {
    extern __shared__ char smc[];
    AttnSmem& s = *reinterpret_cast<AttnSmem*>(smc);

    const int b    = blockIdx.y;
    const int i0   = blockIdx.x * BI;
    const int t    = threadIdx.x;
    const int lane = t & 31;
    const int w    = t >> 5;        // warp 0..3

    if (t < BI) {
        float s2max = dec_f(g_s2max_enc[b]);
        float s1v   = g_s1[(size_t)b * NN + i0 + t];
        s.s1s[t] = s1v;
        s.bss[t] = -fmaxf(0.0f, s1v + s2max) * LOG2E_F;
    }

    float D[16][4];
#pragma unroll
    for (int q = 0; q < 16; ++q)
#pragma unroll
        for (int e = 0; e < 4; ++e) D[q][e] = 0.0f;

    float rowsum[16];
#pragma unroll
    for (int rr = 0; rr < 16; ++rr) rowsum[rr] = 0.0f;

    const __half* hhg  = g_h_hi + (size_t)b * NN * FOUT;
    const float* arow0 = adj + ((size_t)b * NN + i0) * NN;

    const u32 hh_base = smem_u32(&s.hh[0][0][0]);
    const u32 ph_base = smem_u32(&s.ph[0][0][0]);

    // ldmatrix per-lane address components
    const u32 mlow = (lane >> 3) & 1;
    const u32 mhi  = lane >> 4;
    const u32 r8   = lane & 7;
    const u32 aoff = (u32)(w * 16 + mlow * 8 + r8) * (PH_STRIDE * 2) + mhi * 16;
    const u32 boff = (u32)(mlow * 8 + r8) * (HH_STRIDE * 2) + mhi * 16;

    // ---- prologue: group[adj(0)], then group[h(0) -> hh[0]]
    {
#pragma unroll
        for (int r = 0; r < 8; ++r) {
            int v = t + 128 * r;
            int row = v >> 4, q = v & 15;
            cp16(smem_u32(&s.adjb[0][row][q * 4]), arow0 + (size_t)row * NN + q * 4);
        }
        if (t < BJ) cp4(smem_u32(&s.s2s[0][t]), &g_s2[(size_t)b * NN + t]);
        CP_COMMIT();
#pragma unroll
        for (int r = 0; r < 8; ++r) {
            int v = t + 128 * r;              // 0..1023
            int j = v >> 4, q = v & 15;
            cp16(hh_base + (u32)j * (HH_STRIDE * 2) + q * 16,
                 hhg + (size_t)j * FOUT + q * 8);
        }
        CP_COMMIT();
    }

    for (int c = 0; c < NCHUNK; ++c) {
        const int jc  = c * BJ;
        const int buf = c & 1;

        CP_WAIT1();        // own groups: adj(c) + h(c-1) done; h(c) may fly
        __syncthreads();   // publish adj(c), h(c-1), ph(c-1) to ALL threads

        // ---- prefetch adj(c+1) then h(c+1)  [two groups]
        if (c + 1 < NCHUNK) {
            const int nb = buf ^ 1;
            const float* asrc = arow0 + jc + BJ;
#pragma unroll
            for (int r = 0; r < 8; ++r) {
                int v = t + 128 * r;
                int row = v >> 4, q = v & 15;
                cp16(smem_u32(&s.adjb[nb][row][q * 4]), asrc + (size_t)row * NN + q * 4);
            }
            if (t < BJ) cp4(smem_u32(&s.s2s[nb][t]),
                            &g_s2[(size_t)b * NN + jc + BJ + t]);
            CP_COMMIT();
            const u32 hdst = hh_base + (u32)((c + 1) % 3) * HH_BUFB;
            const __half* hsrc = hhg + (size_t)(jc + BJ) * FOUT;
#pragma unroll
            for (int r = 0; r < 8; ++r) {
                int v = t + 128 * r;
                int j = v >> 4, q = v & 15;
                cp16(hdst + (u32)j * (HH_STRIDE * 2) + q * 16,
                     hsrc + (size_t)j * FOUT + q * 8);
            }
            CP_COMMIT();
        }

        // ---- logit(c): warp w rows w*16..+15, lane -> j=2lane,+1
#pragma unroll
        for (int rr = 0; rr < 16; ++rr) {
            const int i = w * 16 + rr;
            const float2 av  = *(const float2*)&s.adjb[buf][i][lane * 2];
            const float2 s2v = *(const float2*)&s.s2s[buf][lane * 2];
            const float  s1v = s.s1s[i];
            const float  bs  = s.bss[i];

            float e0 = s1v + s2v.x,           e1 = s1v + s2v.y;
            float l0 = fmaxf(e0, ALPHA * e0), l1 = fmaxf(e1, ALPHA * e1);
            float r0 = (av.x > 0.0f) ? av.x * l0 : NEG_INFV;
            float r1 = (av.y > 0.0f) ? av.y * l1 : NEG_INFV;
            float p0 = fexp2n(fmaf(r0, LOG2E_F, bs));
            float p1 = fexp2n(fmaf(r1, LOG2E_F, bs));
            p0 = (av.x > 0.0f) ? p0 : 0.0f;
            p1 = (av.y > 0.0f) ? p1 : 0.0f;

            __half2 hx = __floats2half2_rn(p0, p1);
            float2  hf = __half22float2(hx);
            rowsum[rr] += hf.x + hf.y;        // denominator matches fp16 P
            *(__half2*)&s.ph[buf][i][lane * 2] = hx;
        }

        // ---- GEMM(c-1): tensor pipe, overlaps logit issue above
        if (c > 0) {
            gemm_chunk(D, ph_base + (u32)((c - 1) & 1) * PH_BUFB,
                          hh_base + (u32)((c - 1) % 3) * HH_BUFB, aoff, boff);
        }
    }

    // ---- final chunk's GEMM
    CP_WAIT0();
    __syncthreads();   // publish h(63) + ph(63) to all threads
    gemm_chunk(D, ph_base + (u32)((NCHUNK - 1) & 1) * PH_BUFB,
                  hh_base + (u32)((NCHUNK - 1) % 3) * HH_BUFB, aoff, boff);

    // ---- final row-sum reduction
#pragma unroll
    for (int rr = 0; rr < 16; ++rr) {
        float v = rowsum[rr];
#pragma unroll
        for (int off = 16; off; off >>= 1)
            v += __shfl_xor_sync(0xffffffffu, v, off);
        if (lane == 0) s.l[w * 16 + rr] = v;
    }
    __syncthreads();

    // ---- epilogue: normalize, ELU, write (m16n8 D-frag layout)
    {
        const int g   = lane >> 2;
        const int tig = lane & 3;
        const float li0 = 1.0f / s.l[w * 16 + g];
        const float li1 = 1.0f / s.l[w * 16 + g + 8];
        float* o0 = out + ((size_t)b * NN + i0 + w * 16 + g)     * FOUT;
        float* o1 = out + ((size_t)b * NN + i0 + w * 16 + g + 8) * FOUT;
#pragma unroll
        for (int tile = 0; tile < 16; ++tile) {
            const int col = tile * 8 + tig * 2;
            float v0 = D[tile][0] * li0, v1 = D[tile][1] * li0;
            float v2 = D[tile][2] * li1, v3 = D[tile][3] * li1;
            v0 = (v0 > 0.0f) ? v0 : expm1f(v0);
            v1 = (v1 > 0.0f) ? v1 : expm1f(v1);
            v2 = (v2 > 0.0f) ? v2 : expm1f(v2);
            v3 = (v3 > 0.0f) ? v3 : expm1f(v3);
            *(float2*)&o0[col] = make_float2(v0, v1);
            *(float2*)&o1[col] = make_float2(v2, v3);
        }
    }
}

// ---------------------------------------------------------------------------
extern "C" void kernel_launch(void* const* d_in, const int* in_sizes, int n_in,
                              void* d_out, int out_size) {
    const float* inp = (const float*)d_in[0];   // (4,4096,256)
    const float* adj = (const float*)d_in[1];   // (4,4096,4096)
    const float* W   = (const float*)d_in[2];   // (256,128)
    const float* a   = (const float*)d_in[3];   // (256,1)
    float* out = (float*)d_out;                 // (4,4096,128)

    (void)in_sizes; (void)n_in; (void)out_size;

    const int smem_bytes = (int)sizeof(AttnSmem);   // ~105 KB -> 2 CTAs/SM
    cudaFuncSetAttribute(k_attn, cudaFuncAttributeMaxDynamicSharedMemorySize,
                         smem_bytes);

    k_h_gemm<<<(BATCH * NN) / 32, 128>>>(inp, W);
    k_scores<<<(BATCH * NN) / 4, 128>>>(a);

    dim3 grid(NN / BI, BATCH);
    k_attn<<<grid, 128, smem_bytes>>>(adj, out);
}

// round 12
// speedup vs baseline: 1.6996x; 1.6996x over previous
#include <cuda_runtime.h>
#include <cuda_bf16.h>
#include <cuda_fp16.h>
#include <cstdint>
#include <math.h>

#define ALPHA    0.2f
#define NEG_INFV (-1000000000000.0f)
#define LOG2E_F  1.4426950408889634f

#define BATCH 4
#define NN    4096
#define FIN   256
#define FOUT  128

#define BI 64              // query rows per block
#define BJ 64              // key chunk
#define NCHUNK (NN / BJ)   // 64

#define PH_STRIDE 72       // fp16 per P row (144 B, 16B-aligned)
#define HH_STRIDE 136      // fp16 per h row (272 B, 16B-aligned)
#define HH_BUFB   (BJ * HH_STRIDE * 2)   // 17408 B per h buffer
#define PH_BUFB   (BI * PH_STRIDE * 2)   // 9216 B per P buffer

// named barrier ids (0 = __syncthreads)
#define BAR_FULL0 1
#define BAR_FULL1 2
#define BAR_FREE0 3
#define BAR_FREE1 4
#define BAR_PB    5

typedef unsigned long long u64;
typedef unsigned int       u32;

// scratch (device globals: allocation-free)
__device__ float    g_h   [BATCH * NN * FOUT];
__device__ __half   g_h_hi[BATCH * NN * FOUT];
__device__ float    g_s1[BATCH * NN];
__device__ float    g_s2[BATCH * NN];
__device__ unsigned g_s2max_enc[BATCH];

// ---------------------------------------------------------------------------
// helpers
// ---------------------------------------------------------------------------
__device__ __forceinline__ unsigned enc_f(float f) {
    int i = __float_as_int(f);
    unsigned u = (unsigned)i;
    return (i < 0) ? ~u : (u | 0x80000000u);
}
__device__ __forceinline__ float dec_f(unsigned u) {
    int i = (u & 0x80000000u) ? (int)(u & 0x7fffffffu) : (int)~u;
    return __int_as_float(i);
}
__device__ __forceinline__ void ffma2(u64& d, u64 a, u64 b) {
    asm("fma.rn.f32x2 %0, %1, %2, %0;" : "+l"(d) : "l"(a), "l"(b));
}
__device__ __forceinline__ u64 bcast2(float x) {
    u64 r; asm("mov.b64 %0, {%1, %1};" : "=l"(r) : "f"(x)); return r;
}
__device__ __forceinline__ float2 unpack2(u64 v) {
    float2 f; asm("mov.b64 {%0, %1}, %2;" : "=f"(f.x), "=f"(f.y) : "l"(v)); return f;
}
__device__ __forceinline__ float fexp2n(float x) {   // 2^x, x <= 0, FMA-pipe only
    x = fmaxf(x, -126.0f);
    float z = x + 12582912.0f;
    int   n = __float_as_int(z) - 0x4B400000;
    float f = x - (z - 12582912.0f);
    float p = fmaf(0.0013333558f, f, 0.0096181291f);
    p = fmaf(p, f, 0.0555041087f);
    p = fmaf(p, f, 0.2402265070f);
    p = fmaf(p, f, 0.6931471806f);
    p = fmaf(p, f, 1.0f);
    return __int_as_float((n + 127) << 23) * p;
}
__device__ __forceinline__ u32 smem_u32(const void* p) {
    u32 a;
    asm("{ .reg .u64 t; cvta.to.shared.u64 t, %1; cvt.u32.u64 %0, t; }"
        : "=r"(a) : "l"(p));
    return a;
}
__device__ __forceinline__ void cp16(u32 dst, const void* src) {
    asm volatile("cp.async.cg.shared.global [%0], [%1], 16;"
                 :: "r"(dst), "l"(src) : "memory");
}
__device__ __forceinline__ void cp4(u32 dst, const void* src) {
    asm volatile("cp.async.ca.shared.global [%0], [%1], 4;"
                 :: "r"(dst), "l"(src) : "memory");
}
#define CP_COMMIT() asm volatile("cp.async.commit_group;" ::: "memory")
#define CP_WAIT1()  asm volatile("cp.async.wait_group 1;"  ::: "memory")
#define CP_WAIT0()  asm volatile("cp.async.wait_group 0;"  ::: "memory")

__device__ __forceinline__ void bar_sync(int id, int cnt) {
    asm volatile("bar.sync %0, %1;" :: "r"(id), "r"(cnt) : "memory");
}
__device__ __forceinline__ void bar_arrive(int id, int cnt) {
    asm volatile("bar.arrive %0, %1;" :: "r"(id), "r"(cnt) : "memory");
}

__device__ __forceinline__ void ldsm_x4(u32& r0, u32& r1, u32& r2, u32& r3, u32 a) {
    asm volatile("ldmatrix.sync.aligned.m8n8.x4.shared.b16 {%0,%1,%2,%3}, [%4];"
                 : "=r"(r0), "=r"(r1), "=r"(r2), "=r"(r3) : "r"(a));
}
__device__ __forceinline__ void ldsm_x4t(u32& r0, u32& r1, u32& r2, u32& r3, u32 a) {
    asm volatile("ldmatrix.sync.aligned.m8n8.x4.trans.shared.b16 {%0,%1,%2,%3}, [%4];"
                 : "=r"(r0), "=r"(r1), "=r"(r2), "=r"(r3) : "r"(a));
}
__device__ __forceinline__ void mma16816h(float* d,
                                          u32 a0, u32 a1, u32 a2, u32 a3,
                                          u32 b0, u32 b1) {
    asm volatile("mma.sync.aligned.m16n8k16.row.col.f32.f16.f16.f32 "
                 "{%0,%1,%2,%3}, {%4,%5,%6,%7}, {%8,%9}, {%0,%1,%2,%3};"
                 : "+f"(d[0]), "+f"(d[1]), "+f"(d[2]), "+f"(d[3])
                 : "r"(a0), "r"(a1), "r"(a2), "r"(a3), "r"(b0), "r"(b1));
}

// D += P(16x64) @ H(64x128) for one warp
__device__ __forceinline__ void gemm_chunk(float (&D)[16][4],
                                           u32 ph_b, u32 hh_b,
                                           u32 aoff, u32 boff) {
#pragma unroll
    for (int ks = 0; ks < 4; ++ks) {
        u32 a0, a1, a2, a3;
        ldsm_x4(a0, a1, a2, a3, ph_b + aoff + ks * 32);
        const u32 krow = (u32)ks * 16 * (HH_STRIDE * 2);
#pragma unroll
        for (int nt2 = 0; nt2 < 8; ++nt2) {
            u32 b0, b1, b2, b3;
            ldsm_x4t(b0, b1, b2, b3, hh_b + krow + nt2 * 32 + boff);
            mma16816h(D[nt2 * 2],     a0, a1, a2, a3, b0, b1);
            mma16816h(D[nt2 * 2 + 1], a0, a1, a2, a3, b2, b3);
        }
    }
}

// ---------------------------------------------------------------------------
// Kernel 1: h = inp @ W  (fp32x2 GEMM, 64-row tiles); epilogue emits fp16 h
// ---------------------------------------------------------------------------
__global__ void __launch_bounds__(128) k_h_gemm(const float* __restrict__ inp,
                                               const float* __restrict__ W) {
    if (blockIdx.x == 0 && threadIdx.x < BATCH) g_s2max_enc[threadIdx.x] = 0u;

    __shared__ float Ws[32][128];
    __shared__ float Is[64][36];

    const int t  = threadIdx.x;
    const int tx = t & 15;
    const int ty = t >> 4;
    const int m0 = blockIdx.x * 64;

    u64 acc2[8][4];
#pragma unroll
    for (int r = 0; r < 8; ++r)
#pragma unroll
        for (int c = 0; c < 4; ++c) acc2[r][c] = 0ull;

    for (int kc = 0; kc < FIN; kc += 32) {
        __syncthreads();
#pragma unroll
        for (int r = 0; r < 8; ++r) {
            int v = t + 128 * r;
            int k = v >> 5, fq = v & 31;
            *(float4*)&Ws[k][fq * 4] =
                *(const float4*)&W[(size_t)(kc + k) * FOUT + fq * 4];
        }
#pragma unroll
        for (int r = 0; r < 4; ++r) {
            int v = t + 128 * r;
            int m = v >> 3, kq = v & 7;
            *(float4*)&Is[m][kq * 4] =
                *(const float4*)&inp[(size_t)(m0 + m) * FIN + kc + kq * 4];
        }
        __syncthreads();

#pragma unroll
        for (int k = 0; k < 32; ++k) {
            u64 wv2[4];
            {
                ulonglong2 w01 = *(const ulonglong2*)&Ws[k][tx * 4];
                ulonglong2 w23 = *(const ulonglong2*)&Ws[k][64 + tx * 4];
                wv2[0] = w01.x; wv2[1] = w01.y; wv2[2] = w23.x; wv2[3] = w23.y;
            }
            u64 iv2[8];
#pragma unroll
            for (int r = 0; r < 8; ++r) iv2[r] = bcast2(Is[ty * 8 + r][k]);
#pragma unroll
            for (int r = 0; r < 8; ++r)
#pragma unroll
                for (int c = 0; c < 4; ++c)
                    ffma2(acc2[r][c], iv2[r], wv2[c]);
        }
    }

#pragma unroll
    for (int r = 0; r < 8; ++r)
#pragma unroll
        for (int c = 0; c < 4; ++c) {
            int f = (c < 2) ? (tx * 4 + 2 * c) : (64 + tx * 4 + 2 * (c - 2));
            size_t idx = (size_t)(m0 + ty * 8 + r) * FOUT + f;
            float2 v = unpack2(acc2[r][c]);
            g_h[idx]     = v.x;
            g_h[idx + 1] = v.y;
            *(__half2*)&g_h_hi[idx] = __floats2half2_rn(v.x, v.y);
        }
}

// ---------------------------------------------------------------------------
// Kernel 1b: s1, s2, batchwise max(s2)
// ---------------------------------------------------------------------------
__global__ void __launch_bounds__(128) k_scores(const float* __restrict__ a) {
    const int row  = blockIdx.x * 4 + (threadIdx.x >> 5);
    const int lane = threadIdx.x & 31;
    const float* hr = g_h + (size_t)row * FOUT;
    float s1 = 0.f, s2 = 0.f;
#pragma unroll
    for (int k = 0; k < 4; ++k) {
        float hv = hr[lane + 32 * k];
        s1 = fmaf(hv, a[lane + 32 * k], s1);
        s2 = fmaf(hv, a[FOUT + lane + 32 * k], s2);
    }
#pragma unroll
    for (int off = 16; off; off >>= 1) {
        s1 += __shfl_xor_sync(0xffffffffu, s1, off);
        s2 += __shfl_xor_sync(0xffffffffu, s2, off);
    }
    if (lane == 0) {
        g_s1[row] = s1;
        g_s2[row] = s2;
        atomicMax(&g_s2max_enc[row / NN], enc_f(s2));
    }
}

// ---------------------------------------------------------------------------
// Kernel 2: WARP-SPECIALIZED. 256 threads: warps 0-3 producers (adj cp.async
// + logit -> ph), warps 4-7 consumers (h cp.async + ldsm + HMMA). Producer/
// consumer handoff via named barriers: FULL[buf] (producer arrives, consumer
// syncs), FREE[buf] (consumer arrives, producer syncs; pre-armed once each),
// PB (producer-internal publish of cp.async adj tiles). FMA pipe (logit) and
// tensor pipe (HMMA) run CONCURRENTLY on the SM.
// ph[2], hh[2], adjb[3] (adj prefetch depth 2 for the DRAM stream).
// ---------------------------------------------------------------------------
struct AttnSmem {
    __half hh[2][BJ][HH_STRIDE];       // 34816 B
    __half ph[2][BI][PH_STRIDE];       // 18432
    float adjb[3][BI][BJ];             // 49152
    float s2s[3][BJ];                  //   768
    float s1s[BI];                     //   256
    float bss[BI];                     //   256
    float l[BI];                       //   256
};                                     // ~103.9 KB -> 2 CTAs/SM

__global__ void __launch_bounds__(256, 2) k_attn(const float* __restrict__ adj,
                                                 float* __restrict__ out) {
    extern __shared__ char smc[];
    AttnSmem& s = *reinterpret_cast<AttnSmem*>(smc);

    const int b    = blockIdx.y;
    const int i0   = blockIdx.x * BI;
    const int t    = threadIdx.x;
    const int lane = t & 31;
    const int w    = t >> 5;            // 0..7
    const bool producer = (w < 4);

    if (t < BI) {
        float s2max = dec_f(g_s2max_enc[b]);
        float s1v   = g_s1[(size_t)b * NN + i0 + t];
        s.s1s[t] = s1v;
        s.bss[t] = -fmaxf(0.0f, s1v + s2max) * LOG2E_F;
    }

    const __half* hhg  = g_h_hi + (size_t)b * NN * FOUT;
    const float* arow0 = adj + ((size_t)b * NN + i0) * NN;

    const u32 hh_base = smem_u32(&s.hh[0][0][0]);
    const u32 ph_base = smem_u32(&s.ph[0][0][0]);

    // ---- prologue
    if (producer) {
        // stage adj(0)->slot0, adj(1)->slot1 (two groups)
#pragma unroll
        for (int cc = 0; cc < 2; ++cc) {
            const float* asrc = arow0 + cc * BJ;
#pragma unroll
            for (int r = 0; r < 8; ++r) {
                int v = t + 128 * r;
                int row = v >> 4, q = v & 15;
                cp16(smem_u32(&s.adjb[cc][row][q * 4]),
                     asrc + (size_t)row * NN + q * 4);
            }
            if (t < BJ) cp4(smem_u32(&s.s2s[cc][t]),
                            &g_s2[(size_t)b * NN + cc * BJ + t]);
            CP_COMMIT();
        }
    } else {
        // pre-arm FREE barriers so producer's first two FREE syncs pass
        bar_arrive(BAR_FREE0, 256);
        bar_arrive(BAR_FREE1, 256);
        // stage h(0) -> hh[0] (one group)
        const int ct = t - 128;
#pragma unroll
        for (int r = 0; r < 8; ++r) {
            int v = ct + 128 * r;             // 0..1023
            int j = v >> 4, q = v & 15;
            cp16(hh_base + (u32)j * (HH_STRIDE * 2) + q * 16,
                 hhg + (size_t)j * FOUT + q * 8);
        }
        CP_COMMIT();
    }
    __syncthreads();   // publish s1s/bss

    if (producer) {
        float rowsum[16];
#pragma unroll
        for (int rr = 0; rr < 16; ++rr) rowsum[rr] = 0.0f;

        for (int c = 0; c < NCHUNK; ++c) {
            const int buf  = c & 1;
            const int abuf = c % 3;

            if (c + 2 < NCHUNK) CP_WAIT1(); else CP_WAIT0();
            bar_sync(BAR_PB, 128);               // publish adj(c) in group
            bar_sync(BAR_FREE0 + buf, 256);      // ph[buf] free

            // logit(c): warp w rows w*16..+15, lane -> j=2lane,+1
#pragma unroll
            for (int rr = 0; rr < 16; ++rr) {
                const int i = w * 16 + rr;
                const float2 av  = *(const float2*)&s.adjb[abuf][i][lane * 2];
                const float2 s2v = *(const float2*)&s.s2s[abuf][lane * 2];
                const float  s1v = s.s1s[i];
                const float  bs  = s.bss[i];

                float e0 = s1v + s2v.x,           e1 = s1v + s2v.y;
                float l0 = fmaxf(e0, ALPHA * e0), l1 = fmaxf(e1, ALPHA * e1);
                float r0 = (av.x > 0.0f) ? av.x * l0 : NEG_INFV;
                float r1 = (av.y > 0.0f) ? av.y * l1 : NEG_INFV;
                float p0 = fexp2n(fmaf(r0, LOG2E_F, bs));
                float p1 = fexp2n(fmaf(r1, LOG2E_F, bs));
                p0 = (av.x > 0.0f) ? p0 : 0.0f;
                p1 = (av.y > 0.0f) ? p1 : 0.0f;

                __half2 hx = __floats2half2_rn(p0, p1);
                float2  hf = __half22float2(hx);
                rowsum[rr] += hf.x + hf.y;        // denominator matches fp16 P
                *(__half2*)&s.ph[buf][i][lane * 2] = hx;
            }
            bar_arrive(BAR_FULL0 + buf, 256);     // P(c) ready

            // prefetch adj(c+2) (depth 2; slot (c+2)%3 last read at logit(c-1),
            // all producers past it via this chunk's FREE sync)
            if (c + 2 < NCHUNK) {
                const int ns = (c + 2) % 3;
                const float* asrc = arow0 + (size_t)(c + 2) * BJ;
#pragma unroll
                for (int r = 0; r < 8; ++r) {
                    int v = t + 128 * r;
                    int row = v >> 4, q = v & 15;
                    cp16(smem_u32(&s.adjb[ns][row][q * 4]),
                         asrc + (size_t)row * NN + q * 4);
                }
                if (t < BJ) cp4(smem_u32(&s.s2s[ns][t]),
                                &g_s2[(size_t)b * NN + (c + 2) * BJ + t]);
                CP_COMMIT();
            }
        }

        // rowsum reduction -> s.l
#pragma unroll
        for (int rr = 0; rr < 16; ++rr) {
            float v = rowsum[rr];
#pragma unroll
            for (int off = 16; off; off >>= 1)
                v += __shfl_xor_sync(0xffffffffu, v, off);
            if (lane == 0) s.l[w * 16 + rr] = v;
        }
    } else {
        // -------- consumer --------
        const int cw = w - 4;               // 0..3
        const int ct = t - 128;             // 0..127

        float D[16][4];
#pragma unroll
        for (int q = 0; q < 16; ++q)
#pragma unroll
            for (int e = 0; e < 4; ++e) D[q][e] = 0.0f;

        const u32 mlow = (lane >> 3) & 1;
        const u32 mhi  = lane >> 4;
        const u32 r8   = lane & 7;
        const u32 aoff = (u32)(cw * 16 + mlow * 8 + r8) * (PH_STRIDE * 2) + mhi * 16;
        const u32 boff = (u32)(mlow * 8 + r8) * (HH_STRIDE * 2) + mhi * 16;

        for (int c = 0; c < NCHUNK; ++c) {
            const int buf = c & 1;

            CP_WAIT0();                         // h(c) landed (own group)
            bar_sync(BAR_FULL0 + buf, 256);     // P(c) ready; h(c) published;
                                                // all consumers past GEMM(c-1)
            // prefetch h(c+1) into hh[(c+1)&1] (its last readers, GEMM(c-1),
            // are all done per the FULL sync above)
            if (c + 1 < NCHUNK) {
                const u32 hdst = hh_base + (u32)((c + 1) & 1) * HH_BUFB;
                const __half* hsrc = hhg + (size_t)(c + 1) * BJ * FOUT;
#pragma unroll
                for (int r = 0; r < 8; ++r) {
                    int v = ct + 128 * r;
                    int j = v >> 4, q = v & 15;
                    cp16(hdst + (u32)j * (HH_STRIDE * 2) + q * 16,
                         hsrc + (size_t)j * FOUT + q * 8);
                }
                CP_COMMIT();
            }

            gemm_chunk(D, ph_base + (u32)buf * PH_BUFB,
                          hh_base + (u32)(c & 1) * HH_BUFB, aoff, boff);

            bar_arrive(BAR_FREE0 + buf, 256);   // ph[buf] free
        }

        __syncthreads();   // (paired below) — placeholder, see note
        // epilogue: normalize, ELU, write (m16n8 D-frag layout)
        const int g   = lane >> 2;
        const int tig = lane & 3;
        const float li0 = 1.0f / s.l[cw * 16 + g];
        const float li1 = 1.0f / s.l[cw * 16 + g + 8];
        float* o0 = out + ((size_t)b * NN + i0 + cw * 16 + g)     * FOUT;
        float* o1 = out + ((size_t)b * NN + i0 + cw * 16 + g + 8) * FOUT;
#pragma unroll
        for (int tile = 0; tile < 16; ++tile) {
            const int col = tile * 8 + tig * 2;
            float v0 = D[tile][0] * li0, v1 = D[tile][1] * li0;
            float v2 = D[tile][2] * li1, v3 = D[tile][3] * li1;
            v0 = (v0 > 0.0f) ? v0 : expm1f(v0);
            v1 = (v1 > 0.0f) ? v1 : expm1f(v1);
            v2 = (v2 > 0.0f) ? v2 : expm1f(v2);
            v3 = (v3 > 0.0f) ? v3 : expm1f(v3);
            *(float2*)&o0[col] = make_float2(v0, v1);
            *(float2*)&o1[col] = make_float2(v2, v3);
        }
    }

    if (producer) {
        __syncthreads();   // matches consumer's barrier: publishes s.l
    }
}

// ---------------------------------------------------------------------------
extern "C" void kernel_launch(void* const* d_in, const int* in_sizes, int n_in,
                              void* d_out, int out_size) {
    const float* inp = (const float*)d_in[0];   // (4,4096,256)
    const float* adj = (const float*)d_in[1];   // (4,4096,4096)
    const float* W   = (const float*)d_in[2];   // (256,128)
    const float* a   = (const float*)d_in[3];   // (256,1)
    float* out = (float*)d_out;                 // (4,4096,128)

    (void)in_sizes; (void)n_in; (void)out_size;

    const int smem_bytes = (int)sizeof(AttnSmem);   // ~104 KB -> 2 CTAs/SM
    cudaFuncSetAttribute(k_attn, cudaFuncAttributeMaxDynamicSharedMemorySize,
                         smem_bytes);

    k_h_gemm<<<(BATCH * NN) / 64, 128>>>(inp, W);
    k_scores<<<(BATCH * NN) / 4, 128>>>(a);

    dim3 grid(NN / BI, BATCH);
    k_attn<<<grid, 256, smem_bytes>>>(adj, out);
}

// round 13
// speedup vs baseline: 1.7295x; 1.0176x over previous
#include <cuda_runtime.h>
#include <cuda_bf16.h>
#include <cuda_fp16.h>
#include <cstdint>
#include <math.h>

#define ALPHA    0.2f
#define NEG_INFV (-1000000000000.0f)
#define LOG2E_F  1.4426950408889634f

#define BATCH 4
#define NN    4096
#define FIN   256
#define FOUT  128

#define BI 64              // query rows per block
#define BJ 64              // key chunk
#define NCHUNK (NN / BJ)   // 64

#define PH_STRIDE 72       // fp16 per P row (144 B, 16B-aligned)
#define HH_STRIDE 136      // fp16 per h row (272 B, 16B-aligned)
#define HH_BUFB   (BJ * HH_STRIDE * 2)   // 17408 B per h buffer
#define PH_BUFB   (BI * PH_STRIDE * 2)   // 9216 B per P buffer

// named barrier ids (0 = __syncthreads)
#define BAR_FULL0 1
#define BAR_FULL1 2
#define BAR_FREE0 3
#define BAR_FREE1 4

typedef unsigned long long u64;
typedef unsigned int       u32;

// scratch (device globals: allocation-free)
__device__ float    g_h   [BATCH * NN * FOUT];
__device__ __half   g_h_hi[BATCH * NN * FOUT];
__device__ float    g_s1[BATCH * NN];
__device__ float    g_s2[BATCH * NN];
__device__ unsigned g_s2max_enc[BATCH];

// ---------------------------------------------------------------------------
// helpers
// ---------------------------------------------------------------------------
__device__ __forceinline__ unsigned enc_f(float f) {
    int i = __float_as_int(f);
    unsigned u = (unsigned)i;
    return (i < 0) ? ~u : (u | 0x80000000u);
}
__device__ __forceinline__ float dec_f(unsigned u) {
    int i = (u & 0x80000000u) ? (int)(u & 0x7fffffffu) : (int)~u;
    return __int_as_float(i);
}
__device__ __forceinline__ void ffma2(u64& d, u64 a, u64 b) {
    asm("fma.rn.f32x2 %0, %1, %2, %0;" : "+l"(d) : "l"(a), "l"(b));
}
__device__ __forceinline__ u64 bcast2(float x) {
    u64 r; asm("mov.b64 %0, {%1, %1};" : "=l"(r) : "f"(x)); return r;
}
__device__ __forceinline__ float2 unpack2(u64 v) {
    float2 f; asm("mov.b64 {%0, %1}, %2;" : "=f"(f.x), "=f"(f.y) : "l"(v)); return f;
}
__device__ __forceinline__ float fexp2n(float x) {   // 2^x, x <= 0, FMA-pipe only
    x = fmaxf(x, -126.0f);
    float z = x + 12582912.0f;
    int   n = __float_as_int(z) - 0x4B400000;
    float f = x - (z - 12582912.0f);
    float p = fmaf(0.0013333558f, f, 0.0096181291f);
    p = fmaf(p, f, 0.0555041087f);
    p = fmaf(p, f, 0.2402265070f);
    p = fmaf(p, f, 0.6931471806f);
    p = fmaf(p, f, 1.0f);
    return __int_as_float((n + 127) << 23) * p;
}
__device__ __forceinline__ u32 smem_u32(const void* p) {
    u32 a;
    asm("{ .reg .u64 t; cvta.to.shared.u64 t, %1; cvt.u32.u64 %0, t; }"
        : "=r"(a) : "l"(p));
    return a;
}
__device__ __forceinline__ void cp16(u32 dst, const void* src) {
    asm volatile("cp.async.cg.shared.global [%0], [%1], 16;"
                 :: "r"(dst), "l"(src) : "memory");
}
#define CP_COMMIT() asm volatile("cp.async.commit_group;" ::: "memory")
#define CP_WAIT0()  asm volatile("cp.async.wait_group 0;"  ::: "memory")

__device__ __forceinline__ void bar_sync(int id, int cnt) {
    asm volatile("bar.sync %0, %1;" :: "r"(id), "r"(cnt) : "memory");
}
__device__ __forceinline__ void bar_arrive(int id, int cnt) {
    asm volatile("bar.arrive %0, %1;" :: "r"(id), "r"(cnt) : "memory");
}

__device__ __forceinline__ void ldsm_x4(u32& r0, u32& r1, u32& r2, u32& r3, u32 a) {
    asm volatile("ldmatrix.sync.aligned.m8n8.x4.shared.b16 {%0,%1,%2,%3}, [%4];"
                 : "=r"(r0), "=r"(r1), "=r"(r2), "=r"(r3) : "r"(a));
}
__device__ __forceinline__ void ldsm_x4t(u32& r0, u32& r1, u32& r2, u32& r3, u32 a) {
    asm volatile("ldmatrix.sync.aligned.m8n8.x4.trans.shared.b16 {%0,%1,%2,%3}, [%4];"
                 : "=r"(r0), "=r"(r1), "=r"(r2), "=r"(r3) : "r"(a));
}
__device__ __forceinline__ void mma16816h(float* d,
                                          u32 a0, u32 a1, u32 a2, u32 a3,
                                          u32 b0, u32 b1) {
    asm volatile("mma.sync.aligned.m16n8k16.row.col.f32.f16.f16.f32 "
                 "{%0,%1,%2,%3}, {%4,%5,%6,%7}, {%8,%9}, {%0,%1,%2,%3};"
                 : "+f"(d[0]), "+f"(d[1]), "+f"(d[2]), "+f"(d[3])
                 : "r"(a0), "r"(a1), "r"(a2), "r"(a3), "r"(b0), "r"(b1));
}

// ---------------------------------------------------------------------------
// Kernel 1: h = inp @ W  (fp32x2 GEMM, 64-row tiles); epilogue emits fp16 h
// ---------------------------------------------------------------------------
__global__ void __launch_bounds__(128) k_h_gemm(const float* __restrict__ inp,
                                               const float* __restrict__ W) {
    if (blockIdx.x == 0 && threadIdx.x < BATCH) g_s2max_enc[threadIdx.x] = 0u;

    __shared__ float Ws[32][128];
    __shared__ float Is[64][36];

    const int t  = threadIdx.x;
    const int tx = t & 15;
    const int ty = t >> 4;
    const int m0 = blockIdx.x * 64;

    u64 acc2[8][4];
#pragma unroll
    for (int r = 0; r < 8; ++r)
#pragma unroll
        for (int c = 0; c < 4; ++c) acc2[r][c] = 0ull;

    for (int kc = 0; kc < FIN; kc += 32) {
        __syncthreads();
#pragma unroll
        for (int r = 0; r < 8; ++r) {
            int v = t + 128 * r;
            int k = v >> 5, fq = v & 31;
            *(float4*)&Ws[k][fq * 4] =
                *(const float4*)&W[(size_t)(kc + k) * FOUT + fq * 4];
        }
#pragma unroll
        for (int r = 0; r < 4; ++r) {
            int v = t + 128 * r;
            int m = v >> 3, kq = v & 7;
            *(float4*)&Is[m][kq * 4] =
                *(const float4*)&inp[(size_t)(m0 + m) * FIN + kc + kq * 4];
        }
        __syncthreads();

#pragma unroll
        for (int k = 0; k < 32; ++k) {
            u64 wv2[4];
            {
                ulonglong2 w01 = *(const ulonglong2*)&Ws[k][tx * 4];
                ulonglong2 w23 = *(const ulonglong2*)&Ws[k][64 + tx * 4];
                wv2[0] = w01.x; wv2[1] = w01.y; wv2[2] = w23.x; wv2[3] = w23.y;
            }
            u64 iv2[8];
#pragma unroll
            for (int r = 0; r < 8; ++r) iv2[r] = bcast2(Is[ty * 8 + r][k]);
#pragma unroll
            for (int r = 0; r < 8; ++r)
#pragma unroll
                for (int c = 0; c < 4; ++c)
                    ffma2(acc2[r][c], iv2[r], wv2[c]);
        }
    }

#pragma unroll
    for (int r = 0; r < 8; ++r)
#pragma unroll
        for (int c = 0; c < 4; ++c) {
            int f = (c < 2) ? (tx * 4 + 2 * c) : (64 + tx * 4 + 2 * (c - 2));
            size_t idx = (size_t)(m0 + ty * 8 + r) * FOUT + f;
            float2 v = unpack2(acc2[r][c]);
            g_h[idx]     = v.x;
            g_h[idx + 1] = v.y;
            *(__half2*)&g_h_hi[idx] = __floats2half2_rn(v.x, v.y);
        }
}

// ---------------------------------------------------------------------------
// Kernel 1b: s1, s2, batchwise max(s2)
// ---------------------------------------------------------------------------
__global__ void __launch_bounds__(128) k_scores(const float* __restrict__ a) {
    const int row  = blockIdx.x * 4 + (threadIdx.x >> 5);
    const int lane = threadIdx.x & 31;
    const float* hr = g_h + (size_t)row * FOUT;
    float s1 = 0.f, s2 = 0.f;
#pragma unroll
    for (int k = 0; k < 4; ++k) {
        float hv = hr[lane + 32 * k];
        s1 = fmaf(hv, a[lane + 32 * k], s1);
        s2 = fmaf(hv, a[FOUT + lane + 32 * k], s2);
    }
#pragma unroll
    for (int off = 16; off; off >>= 1) {
        s1 += __shfl_xor_sync(0xffffffffu, s1, off);
        s2 += __shfl_xor_sync(0xffffffffu, s2, off);
    }
    if (lane == 0) {
        g_s1[row] = s1;
        g_s2[row] = s2;
        atomicMax(&g_s2max_enc[row / NN], enc_f(s2));
    }
}

// ---------------------------------------------------------------------------
// Kernel 2: warp-specialized, crossbar-minimized.
//  - producers (warps 0-3): adj via DIRECT __ldg (never touches smem),
//    per-row constants in registers, logit -> ph[buf]
//  - consumers (warps 4-7): N-SPLIT — warp cw computes all 64 rows x its own
//    32 cols, so H ldsm traffic is 4 KB/warp/chunk instead of 16 KB
// Handoff: FULL[buf] (producers arrive / consumers sync),
//          FREE[buf] (consumers arrive / producers sync; pre-armed x2).
// ---------------------------------------------------------------------------
struct AttnSmem {
    __half hh[2][BJ][HH_STRIDE];       // 34816 B
    __half ph[2][BI][PH_STRIDE];       // 18432
    float l[BI];                       //   256
};                                     // ~53.5 KB -> 2 CTAs/SM

__global__ void __launch_bounds__(256, 2) k_attn(const float* __restrict__ adj,
                                                 float* __restrict__ out) {
    extern __shared__ char smc[];
    AttnSmem& s = *reinterpret_cast<AttnSmem*>(smc);

    const int b    = blockIdx.y;
    const int i0   = blockIdx.x * BI;
    const int t    = threadIdx.x;
    const int lane = t & 31;
    const int w    = t >> 5;            // 0..7
    const bool producer = (w < 4);

    const __half* hhg  = g_h_hi + (size_t)b * NN * FOUT;
    const float* arow0 = adj + ((size_t)b * NN + i0) * NN;

    const u32 hh_base = smem_u32(&s.hh[0][0][0]);
    const u32 ph_base = smem_u32(&s.ph[0][0][0]);

    if (producer) {
        // ---- per-row constants in registers
        const float s2max = dec_f(g_s2max_enc[b]);
        float s1r[16], bsr[16], rowsum[16];
#pragma unroll
        for (int rr = 0; rr < 16; ++rr) {
            float v = __ldg(&g_s1[(size_t)b * NN + i0 + w * 16 + rr]);
            s1r[rr]    = v;
            bsr[rr]    = -fmaxf(0.0f, v + s2max) * LOG2E_F;
            rowsum[rr] = 0.0f;
        }
        __syncthreads();   // prologue pairing with consumers

        const float2* s2p = (const float2*)(g_s2 + (size_t)b * NN);

        for (int c = 0; c < NCHUNK; ++c) {
            const int buf = c & 1;
            const int jc  = c * BJ;

            bar_sync(BAR_FREE0 + buf, 256);      // ph[buf] free

            const float2 s2v = __ldg(s2p + (jc >> 1) + lane);
            const float  e0c = s2v.x, e1c = s2v.y;

#pragma unroll
            for (int half = 0; half < 2; ++half) {
                // batch 8 adj loads (MLP=8), then compute 8 rows
                float2 av[8];
#pragma unroll
                for (int rb = 0; rb < 8; ++rb) {
                    const int i = w * 16 + half * 8 + rb;
                    av[rb] = __ldg((const float2*)(arow0 + (size_t)i * NN + jc)
                                   + lane);
                }
#pragma unroll
                for (int rb = 0; rb < 8; ++rb) {
                    const int rr = half * 8 + rb;
                    const int i  = w * 16 + rr;
                    const float s1v = s1r[rr];
                    const float bs  = bsr[rr];

                    float e0 = s1v + e0c,             e1 = s1v + e1c;
                    float l0 = fmaxf(e0, ALPHA * e0), l1 = fmaxf(e1, ALPHA * e1);
                    float r0 = (av[rb].x > 0.0f) ? av[rb].x * l0 : NEG_INFV;
                    float r1 = (av[rb].y > 0.0f) ? av[rb].y * l1 : NEG_INFV;
                    float p0 = fexp2n(fmaf(r0, LOG2E_F, bs));
                    float p1 = fexp2n(fmaf(r1, LOG2E_F, bs));
                    p0 = (av[rb].x > 0.0f) ? p0 : 0.0f;
                    p1 = (av[rb].y > 0.0f) ? p1 : 0.0f;

                    __half2 hx = __floats2half2_rn(p0, p1);
                    float2  hf = __half22float2(hx);
                    rowsum[rr] += hf.x + hf.y;    // denominator matches fp16 P
                    *(__half2*)&s.ph[buf][i][lane * 2] = hx;
                }
            }
            bar_arrive(BAR_FULL0 + buf, 256);     // P(c) ready
        }

        // rowsum reduction -> s.l
#pragma unroll
        for (int rr = 0; rr < 16; ++rr) {
            float v = rowsum[rr];
#pragma unroll
            for (int off = 16; off; off >>= 1)
                v += __shfl_xor_sync(0xffffffffu, v, off);
            if (lane == 0) s.l[w * 16 + rr] = v;
        }
        __syncthreads();   // publish s.l (paired with consumer)
    } else {
        // -------- consumer: N-split --------
        const int cw = w - 4;               // 0..3: cols cw*32 .. cw*32+31
        const int ct = t - 128;             // 0..127

        // pre-arm FREE barriers; stage h(0) -> hh[0]
        bar_arrive(BAR_FREE0, 256);
        bar_arrive(BAR_FREE1, 256);
#pragma unroll
        for (int r = 0; r < 8; ++r) {
            int v = ct + 128 * r;             // 0..1023
            int j = v >> 4, q = v & 15;
            cp16(hh_base + (u32)j * (HH_STRIDE * 2) + q * 16,
                 hhg + (size_t)j * FOUT + q * 8);
        }
        CP_COMMIT();
        __syncthreads();   // prologue pairing with producers

        float D[4][4][4];   // [mt][n8][elem]
#pragma unroll
        for (int mt = 0; mt < 4; ++mt)
#pragma unroll
            for (int n8 = 0; n8 < 4; ++n8)
#pragma unroll
                for (int e = 0; e < 4; ++e) D[mt][n8][e] = 0.0f;

        const u32 mlow  = (lane >> 3) & 1;
        const u32 mhi   = lane >> 4;
        const u32 r8    = lane & 7;
        const u32 abase = (u32)(mlow * 8 + r8) * (PH_STRIDE * 2) + mhi * 16;
        const u32 bbase = (u32)(mlow * 8 + r8) * (HH_STRIDE * 2) + mhi * 16;

        for (int c = 0; c < NCHUNK; ++c) {
            const int buf = c & 1;

            CP_WAIT0();                         // h(c) landed (own group)
            bar_sync(BAR_FULL0 + buf, 256);     // P(c) ready; h(c) published;
                                                // all consumers past GEMM(c-1)
            // prefetch h(c+1) into hh[(c+1)&1]
            if (c + 1 < NCHUNK) {
                const u32 hdst = hh_base + (u32)((c + 1) & 1) * HH_BUFB;
                const __half* hsrc = hhg + (size_t)(c + 1) * BJ * FOUT;
#pragma unroll
                for (int r = 0; r < 8; ++r) {
                    int v = ct + 128 * r;
                    int j = v >> 4, q = v & 15;
                    cp16(hdst + (u32)j * (HH_STRIDE * 2) + q * 16,
                         hsrc + (size_t)j * FOUT + q * 8);
                }
                CP_COMMIT();
            }

            // GEMM(c): D += P(64x64) @ H(64x[cw*32..+31])
            const u32 ph_b = ph_base + (u32)buf * PH_BUFB;
            const u32 hh_b = hh_base + (u32)(c & 1) * HH_BUFB;
#pragma unroll
            for (int ks = 0; ks < 4; ++ks) {
                const u32 krow = (u32)ks * 16 * (HH_STRIDE * 2);
                u32 b00, b01, b02, b03, b10, b11, b12, b13;
                ldsm_x4t(b00, b01, b02, b03,
                         hh_b + krow + (u32)(2 * cw + 0) * 32 + bbase);
                ldsm_x4t(b10, b11, b12, b13,
                         hh_b + krow + (u32)(2 * cw + 1) * 32 + bbase);
#pragma unroll
                for (int mt = 0; mt < 4; ++mt) {
                    u32 a0, a1, a2, a3;
                    ldsm_x4(a0, a1, a2, a3,
                            ph_b + (u32)(mt * 16) * (PH_STRIDE * 2)
                                 + abase + ks * 32);
                    mma16816h(D[mt][0], a0, a1, a2, a3, b00, b01);
                    mma16816h(D[mt][1], a0, a1, a2, a3, b02, b03);
                    mma16816h(D[mt][2], a0, a1, a2, a3, b10, b11);
                    mma16816h(D[mt][3], a0, a1, a2, a3, b12, b13);
                }
            }

            bar_arrive(BAR_FREE0 + buf, 256);   // ph[buf] free
        }

        __syncthreads();   // s.l published by producers

        // epilogue: normalize, ELU, write
        const int g   = lane >> 2;
        const int tig = lane & 3;
#pragma unroll
        for (int mt = 0; mt < 4; ++mt) {
            const int row0 = mt * 16 + g;
            const float li0 = 1.0f / s.l[row0];
            const float li1 = 1.0f / s.l[row0 + 8];
            float* o0 = out + ((size_t)b * NN + i0 + row0)     * FOUT;
            float* o1 = out + ((size_t)b * NN + i0 + row0 + 8) * FOUT;
#pragma unroll
            for (int n8 = 0; n8 < 4; ++n8) {
                const int col = cw * 32 + n8 * 8 + tig * 2;
                float v0 = D[mt][n8][0] * li0, v1 = D[mt][n8][1] * li0;
                float v2 = D[mt][n8][2] * li1, v3 = D[mt][n8][3] * li1;
                v0 = (v0 > 0.0f) ? v0 : expm1f(v0);
                v1 = (v1 > 0.0f) ? v1 : expm1f(v1);
                v2 = (v2 > 0.0f) ? v2 : expm1f(v2);
                v3 = (v3 > 0.0f) ? v3 : expm1f(v3);
                *(float2*)&o0[col] = make_float2(v0, v1);
                *(float2*)&o1[col] = make_float2(v2, v3);
            }
        }
    }
}

// ---------------------------------------------------------------------------
extern "C" void kernel_launch(void* const* d_in, const int* in_sizes, int n_in,
                              void* d_out, int out_size) {
    const float* inp = (const float*)d_in[0];   // (4,4096,256)
    const float* adj = (const float*)d_in[1];   // (4,4096,4096)
    const float* W   = (const float*)d_in[2];   // (256,128)
    const float* a   = (const float*)d_in[3];   // (256,1)
    float* out = (float*)d_out;                 // (4,4096,128)

    (void)in_sizes; (void)n_in; (void)out_size;

    const int smem_bytes = (int)sizeof(AttnSmem);   // ~53.5 KB -> 2 CTAs/SM
    cudaFuncSetAttribute(k_attn, cudaFuncAttributeMaxDynamicSharedMemorySize,
                         smem_bytes);

    k_h_gemm<<<(BATCH * NN) / 64, 128>>>(inp, W);
    k_scores<<<(BATCH * NN) / 4, 128>>>(a);

    dim3 grid(NN / BI, BATCH);
    k_attn<<<grid, 256, smem_bytes>>>(adj, out);
}